// round 7
// baseline (speedup 1.0000x reference)
#include <cuda_runtime.h>
#include <cuda_bf16.h>
#include <stdint.h>

// ---------------- problem constants (fixed shapes) ----------------
#define DD   128
#define HH   192
#define WP   193            // pred_z last-dim
#define WW   192            // d last-dim (WP-1)
#define TOTD (DD*HH*WW)     // 4,718,592
#define N0   (DD*HH)        // 24,576 first-slice elements
#define RANK ((N0-1)/2)     // 12,287 (lower median, 0-based)

// ---------------- device scratch (no allocations allowed) ----------------
__device__ float    g_d[TOTD];          // the diff volume
__device__ double   g_sum;              // sum of (d-med)^2
__device__ unsigned g_mon;              // float bits of max(relu(1-dz)) (>=0 -> uint-orderable)
__device__ int      g_hist[1024];       // radix histogram (top 10 bits of sortable key)
__device__ int      g_bucket;           // selected bucket
__device__ int      g_rank;             // rank within bucket
__device__ unsigned g_cand[N0];         // candidate keys
__device__ int      g_ccount;

// ---------------- helpers ----------------
__device__ __forceinline__ int refl(int i, int n) {
    // jnp.pad mode='reflect': -1 -> 1, n -> n-2 (only +-1 needed here)
    return (i < 0) ? -i : ((i >= n) ? (2*n - 2 - i) : i);
}

__device__ __forceinline__ void ce(float& x, float& y) {
    float mn = fminf(x, y);
    float mx = fmaxf(x, y);
    x = mn; y = mx;
}

__device__ __forceinline__ unsigned f2key(float f) {
    unsigned u = __float_as_uint(f);
    return (u & 0x80000000u) ? ~u : (u | 0x80000000u);
}
__device__ __forceinline__ float key2f(unsigned k) {
    unsigned u = (k & 0x80000000u) ? (k & 0x7fffffffu) : ~k;
    return __uint_as_float(u);
}

// Exact median of 27 via forgetful selection: buffer 15, 12 insertion rounds.
// Validity: buffer size 15 > 27 - 13 - 1 + ... (standard (n+3)/2 bound), so the
// running min/max dropped each round can never be the rank-13 element.
__device__ __forceinline__ float median27(const float a[9], const float b[9], const float c[9]) {
    float B[15];
#pragma unroll
    for (int j = 0; j < 9; j++) B[j] = a[j];
#pragma unroll
    for (int j = 0; j < 6; j++) B[9 + j] = b[j];
    float ins[12];
    ins[0] = b[6]; ins[1] = b[7]; ins[2] = b[8];
#pragma unroll
    for (int j = 0; j < 9; j++) ins[3 + j] = c[j];

#pragma unroll
    for (int s = 0; s < 12; s++) {
        const int L = 15 - s;          // current logical buffer length
        // forward bubble: max -> B[L-1]
#pragma unroll
        for (int i = 0; i < L - 1; i++) ce(B[i], B[i + 1]);
        // backward bubble: min -> B[0]  (doesn't touch B[L-1])
#pragma unroll
        for (int i = L - 2; i >= 1; i--) ce(B[i - 1], B[i]);
        // drop min (B[0]) and max (B[L-1]): overwrite min, shrink length
        B[0] = ins[s];
    }
    // 3 survivors in B[0..2]; their median is global rank 13
    float lo = fminf(B[0], B[1]);
    float hi = fmaxf(B[0], B[1]);
    return fmaxf(lo, fminf(hi, B[2]));
}

// ---------------- kernels ----------------
__global__ void k_init() {
    int t = threadIdx.x;
    if (t == 0) { g_sum = 0.0; g_mon = 0u; g_ccount = 0; }
    if (t < 1024) g_hist[t] = 0;
}

// d = diff along W, plus global max(relu(1 - dz))
__global__ void k_diff(const float* __restrict__ p) {
    int i = blockIdx.x * blockDim.x + threadIdx.x;   // grid covers TOTD exactly
    float lm = 0.0f;
    if (i < TOTD) {
        int x   = i % WW;
        int row = i / WW;                            // row in [0, DD*HH)
        float lo = p[(size_t)row * WP + x];
        float hi = p[(size_t)row * WP + x + 1];
        float v  = hi - lo;
        g_d[i] = v;
        lm = fmaxf(1.0f - v, 0.0f);
    }
#pragma unroll
    for (int off = 16; off; off >>= 1)
        lm = fmaxf(lm, __shfl_xor_sync(0xffffffffu, lm, off));
    __shared__ float sred[8];
    if ((threadIdx.x & 31) == 0) sred[threadIdx.x >> 5] = lm;
    __syncthreads();
    if (threadIdx.x < 8) {
        float v2 = sred[threadIdx.x];
#pragma unroll
        for (int off = 4; off; off >>= 1)
            v2 = fmaxf(v2, __shfl_xor_sync(0xffu, v2, off));
        if (threadIdx.x == 0) atomicMax(&g_mon, __float_as_uint(v2));
    }
}

// 3x3x3 median + squared-residual sum.
// Block (32,4) covers a 32x4 (x,y) tile; each thread rolls a z-column through a
// 32-deep chunk keeping its 3x3 neighborhoods for planes z-1,z,z+1 in registers.
// Only the new plane is staged through a small shared tile (9 LDS/voxel).
#define TX 32
#define TY 4
#define ZCHUNK 32
__global__ __launch_bounds__(TX*TY) void k_median() {
    __shared__ float sm[TY + 2][TX + 2];
    const int tx = threadIdx.x, ty = threadIdx.y;
    const int tid = ty * TX + tx;
    const int gx0 = blockIdx.x * TX;
    const int gy0 = blockIdx.y * TY;
    const int z0  = blockIdx.z * ZCHUNK;

    float a[9], b[9], c[9];

    auto load_plane = [&](int z) {
        const int zr = refl(z, DD);
        const float* base = g_d + (size_t)zr * HH * WW;
        for (int idx = tid; idx < (TY + 2) * (TX + 2); idx += TX * TY) {
            int yy = idx / (TX + 2);
            int xx = idx % (TX + 2);
            int gy = refl(gy0 - 1 + yy, HH);
            int gx = refl(gx0 - 1 + xx, WW);
            sm[yy][xx] = base[(size_t)gy * WW + gx];
        }
    };

    load_plane(z0 - 1);
    __syncthreads();
#pragma unroll
    for (int j = 0; j < 9; j++) a[j] = sm[ty + j / 3][tx + j % 3];
    __syncthreads();
    load_plane(z0);
    __syncthreads();
#pragma unroll
    for (int j = 0; j < 9; j++) b[j] = sm[ty + j / 3][tx + j % 3];

    float lsum = 0.0f;
    for (int z = z0; z < z0 + ZCHUNK; z++) {
        __syncthreads();              // all reads of previous plane done
        load_plane(z + 1);
        __syncthreads();
#pragma unroll
        for (int j = 0; j < 9; j++) c[j] = sm[ty + j / 3][tx + j % 3];

        float med  = median27(a, b, c);
        float diff = b[4] - med;      // center voxel value
        lsum += diff * diff;

#pragma unroll
        for (int j = 0; j < 9; j++) { a[j] = b[j]; b[j] = c[j]; }
    }

    // block reduction of lsum
    __shared__ float red[TX * TY];
    red[tid] = lsum;
    __syncthreads();
#pragma unroll
    for (int s = (TX * TY) / 2; s > 0; s >>= 1) {
        if (tid < s) red[tid] += red[tid + s];
        __syncthreads();
    }
    if (tid == 0) atomicAdd(&g_sum, (double)red[0]);
}

// ---- global median of first-slice values via radix select ----
__global__ void k_hist(const float* __restrict__ p) {
    int i = blockIdx.x * blockDim.x + threadIdx.x;
    if (i < N0) {
        unsigned key = f2key(p[(size_t)i * WP]);
        atomicAdd(&g_hist[key >> 22], 1);
    }
}

__global__ void k_scan() {
    __shared__ int s[1024];
    int t = threadIdx.x;
    int h = g_hist[t];
    s[t] = h;
    __syncthreads();
    for (int off = 1; off < 1024; off <<= 1) {
        int v = (t >= off) ? s[t - off] : 0;
        __syncthreads();
        s[t] += v;
        __syncthreads();
    }
    int incl = s[t];
    int excl = incl - h;
    if (excl <= RANK && RANK < incl) {
        g_bucket = t;
        g_rank   = RANK - excl;
    }
}

__global__ void k_gather(const float* __restrict__ p) {
    int i = blockIdx.x * blockDim.x + threadIdx.x;
    int bkt = g_bucket;
    if (i < N0) {
        unsigned key = f2key(p[(size_t)i * WP]);
        if ((int)(key >> 22) == bkt) {
            int pos = atomicAdd(&g_ccount, 1);
            g_cand[pos] = key;
        }
    }
}

__global__ void k_select(float* __restrict__ out) {
    int m = g_ccount;
    int r = g_rank;
    for (int i = threadIdx.x; i < m; i += blockDim.x) {
        unsigned ki = g_cand[i];
        int less = 0, eq = 0;
        for (int j = 0; j < m; j++) {
            unsigned kj = g_cand[j];
            less += (kj < ki);
            eq   += (kj == ki);
        }
        if (less <= r && r < less + eq) {
            float v = key2f(ki);
            out[2] = v * v;           // loss_average
        }
    }
}

__global__ void k_finalize(float* __restrict__ out) {
    out[0] = (float)(g_sum * (1.0 / (double)TOTD));  // loss_smooth
    out[1] = __uint_as_float(g_mon);                 // loss_mon
}

// ---------------- launch ----------------
extern "C" void kernel_launch(void* const* d_in, const int* in_sizes, int n_in,
                              void* d_out, int out_size) {
    const float* p = (const float*)d_in[0];
    float* out = (float*)d_out;

    k_init<<<1, 1024>>>();
    k_diff<<<TOTD / 256, 256>>>(p);
    {
        dim3 grid(WW / TX, HH / TY, DD / ZCHUNK);   // 6 x 48 x 4 = 1152 blocks
        dim3 block(TX, TY);
        k_median<<<grid, block>>>();
    }
    k_hist<<<(N0 + 255) / 256, 256>>>(p);
    k_scan<<<1, 1024>>>();
    k_gather<<<(N0 + 255) / 256, 256>>>(p);
    k_select<<<1, 256>>>(out);
    k_finalize<<<1, 1>>>(out);
}

// round 8
// speedup vs baseline: 2.6583x; 2.6583x over previous
#include <cuda_runtime.h>
#include <cuda_bf16.h>
#include <stdint.h>

// ---------------- problem constants (fixed shapes) ----------------
#define DD   128
#define HH   192
#define WP   193            // pred_z last-dim
#define WW   192            // d last-dim (WP-1)
#define TOTD (DD*HH*WW)     // 4,718,592
#define N0   (DD*HH)        // 24,576 first-slice elements
#define RANK ((N0-1)/2)     // 12,287 (lower median, 0-based)

// ---------------- device scratch (no allocations allowed) ----------------
__device__ double   g_sum;              // sum of (d-med)^2
__device__ unsigned g_mon;              // float bits of max(relu(1-dz))
__device__ int      g_hist[1024];       // radix histogram (top 10 bits of key)
__device__ unsigned g_z0[N0];           // staged sortable keys of first-slice values
__device__ unsigned g_cand[N0];         // candidate keys
__device__ int      g_ccount;

// ---------------- helpers ----------------
__device__ __forceinline__ int refl(int i, int n) {
    return (i < 0) ? -i : ((i >= n) ? (2*n - 2 - i) : i);
}

__device__ __forceinline__ void ce(float& a, float& b) {
    float mn = fminf(a, b);
    float mx = fmaxf(a, b);
    a = mn; b = mx;
}

__device__ __forceinline__ unsigned f2key(float f) {
    unsigned u = __float_as_uint(f);
    return (u & 0x80000000u) ? ~u : (u | 0x80000000u);
}
__device__ __forceinline__ float key2f(unsigned k) {
    unsigned u = (k & 0x80000000u) ? (k & 0x7fffffffu) : ~k;
    return __uint_as_float(u);
}

// ---------- sorting / merging networks (Batcher odd-even, arbitrary sizes) ----------
__device__ __forceinline__ void sort3(float&a,float&b,float&c){ ce(a,b); ce(a,c); ce(b,c); }
__device__ __forceinline__ void sort4(float&a,float&b,float&c,float&d){
    ce(a,b); ce(c,d); ce(a,c); ce(b,d); ce(b,c);
}

// merge sorted (a0) with sorted (b0,b1) -> z[0..2]
__device__ __forceinline__ void merge12(float a0,float b0,float b1,float z[3]){
    float v0=fminf(a0,b0), v1=fmaxf(a0,b0);
    z[0]=v0; z[1]=fminf(b1,v1); z[2]=fmaxf(b1,v1);
}
// merge sorted (a0,a1) with (b0,b1) -> z[0..3]
__device__ __forceinline__ void merge22(float a0,float a1,float b0,float b1,float z[4]){
    float v0=fminf(a0,b0), v1=fmaxf(a0,b0);
    float w0=fminf(a1,b1), w1=fmaxf(a1,b1);
    z[0]=v0; z[1]=fminf(w0,v1); z[2]=fmaxf(w0,v1); z[3]=w1;
}
// merge sorted (a0,a1) with (b0,b1,b2) -> z[0..4]
__device__ __forceinline__ void merge23(float a0,float a1,float b0,float b1,float b2,float z[5]){
    float v[3]; merge12(a0,b0,b2,v);
    float w0=fminf(a1,b1), w1=fmaxf(a1,b1);
    z[0]=v[0];
    z[1]=fminf(w0,v[1]); z[2]=fmaxf(w0,v[1]);
    z[3]=fminf(w1,v[2]); z[4]=fmaxf(w1,v[2]);
}
// merge sorted (a0..a2) with (b0..b2) -> z[0..5]
__device__ __forceinline__ void merge33(float a0,float a1,float a2,float b0,float b1,float b2,float z[6]){
    float v[4]; merge22(a0,a2,b0,b2,v);
    float w0=fminf(a1,b1), w1=fmaxf(a1,b1);
    z[0]=v[0];
    z[1]=fminf(w0,v[1]); z[2]=fmaxf(w0,v[1]);
    z[3]=fminf(w1,v[2]); z[4]=fmaxf(w1,v[2]);
    z[5]=v[3];
}
// merge sorted (a0..a3) with (b0..b3) -> z[0..7]
__device__ __forceinline__ void merge44(float a0,float a1,float a2,float a3,
                                        float b0,float b1,float b2,float b3,float z[8]){
    float v[4]; merge22(a0,a2,b0,b2,v);
    float w[4]; merge22(a1,a3,b1,b3,w);
    z[0]=v[0];
    z[1]=fminf(w[0],v[1]); z[2]=fmaxf(w[0],v[1]);
    z[3]=fminf(w[1],v[2]); z[4]=fmaxf(w[1],v[2]);
    z[5]=fminf(w[2],v[3]); z[6]=fmaxf(w[2],v[3]);
    z[7]=w[3];
}
// merge sorted (a0..a3) with (b0..b4) -> z[0..8]
__device__ __forceinline__ void merge45(float a0,float a1,float a2,float a3,
                                        float b0,float b1,float b2,float b3,float b4,float z[9]){
    float v[5]; merge23(a0,a2,b0,b2,b4,v);
    float w[4]; merge22(a1,a3,b1,b3,w);
    z[0]=v[0];
    z[1]=fminf(w[0],v[1]); z[2]=fmaxf(w[0],v[1]);
    z[3]=fminf(w[1],v[2]); z[4]=fmaxf(w[1],v[2]);
    z[5]=fminf(w[2],v[3]); z[6]=fmaxf(w[2],v[3]);
    z[7]=fminf(w[3],v[4]); z[8]=fmaxf(w[3],v[4]);
}
// merge sorted (a0..a4) with (b0..b4) -> z[0..9]
__device__ __forceinline__ void merge55(float a0,float a1,float a2,float a3,float a4,
                                        float b0,float b1,float b2,float b3,float b4,float z[10]){
    float v[6]; merge33(a0,a2,a4,b0,b2,b4,v);
    float w[4]; merge22(a1,a3,b1,b3,w);
    z[0]=v[0];
    z[1]=fminf(w[0],v[1]); z[2]=fmaxf(w[0],v[1]);
    z[3]=fminf(w[1],v[2]); z[4]=fmaxf(w[1],v[2]);
    z[5]=fminf(w[2],v[3]); z[6]=fmaxf(w[2],v[3]);
    z[7]=fminf(w[3],v[4]); z[8]=fmaxf(w[3],v[4]);
    z[9]=v[5];
}

// in-place sort of 9 (odd-even mergesort: sort4 + sort5 + merge45, 26 CE)
__device__ __forceinline__ void sort9(float p[9]){
    sort4(p[0],p[1],p[2],p[3]);
    ce(p[4],p[5]);
    sort3(p[6],p[7],p[8]);
    { float q[5]; merge23(p[4],p[5],p[6],p[7],p[8],q);
      p[4]=q[0]; p[5]=q[1]; p[6]=q[2]; p[7]=q[3]; p[8]=q[4]; }
    float s[9]; merge45(p[0],p[1],p[2],p[3],p[4],p[5],p[6],p[7],p[8],s);
#pragma unroll
    for(int i=0;i<9;i++) p[i]=s[i];
}

// middle outputs z[4..13] of odd-even merge(9,9) of sorted A, B  -> mid[0..9]
__device__ __forceinline__ void merge99_mid(const float A[9], const float B[9], float mid[10]){
    float v[10], w[8];
    merge55(A[0],A[2],A[4],A[6],A[8], B[0],B[2],B[4],B[6],B[8], v);
    merge44(A[1],A[3],A[5],A[7],      B[1],B[3],B[5],B[7],      w);
    // z[2i+1]=min(w[i],v[i+1]); z[2i+2]=max(w[i],v[i+1]); need z4..z13
    mid[0]=fmaxf(w[1],v[2]);                          // z4
    mid[1]=fminf(w[2],v[3]); mid[2]=fmaxf(w[2],v[3]); // z5,z6
    mid[3]=fminf(w[3],v[4]); mid[4]=fmaxf(w[3],v[4]); // z7,z8
    mid[5]=fminf(w[4],v[5]); mid[6]=fmaxf(w[4],v[5]); // z9,z10
    mid[7]=fminf(w[5],v[6]); mid[8]=fmaxf(w[5],v[6]); // z11,z12
    mid[9]=fminf(w[6],v[7]);                          // z13
}

// rank-13 (0-based) of 27 = 14th smallest of (sorted-18 AB given via AB[4..13]=mid) u (sorted-9 C)
// identity: r-th smallest of two sorted arrays = min over splits i+j=r of max(lasts)
__device__ __forceinline__ float select13(const float mid[10], const float C[9]){
    float t0 = fminf(fmaxf(mid[0],C[8]), fmaxf(mid[1],C[7]));
    float t1 = fminf(fmaxf(mid[2],C[6]), fmaxf(mid[3],C[5]));
    float t2 = fminf(fmaxf(mid[4],C[4]), fmaxf(mid[5],C[3]));
    float t3 = fminf(fmaxf(mid[6],C[2]), fmaxf(mid[7],C[1]));
    float t4 = fminf(fmaxf(mid[8],C[0]), mid[9]);
    return fminf(fminf(fminf(t0,t1), fminf(t2,t3)), t4);
}

// ---------------- median kernel (fused diff + mon + median + residual sum) ----------------
#define TX 32
#define TY 4
#define ZC 16
__global__ __launch_bounds__(TX*TY) void k_median(const float* __restrict__ p){
    __shared__ float sm[2][TY+2][TX+2];
    const int tx = threadIdx.x, ty = threadIdx.y;
    const int tid = ty*TX + tx;
    const int gx0 = blockIdx.x*TX;
    const int gy0 = blockIdx.y*TY;
    const int z0  = blockIdx.z*ZC;

    // stage one z-plane of d (with reflect in y,x) into smem buffer `buf`
    auto load_plane = [&](int z, int buf){
        const int zr = refl(z, DD);
        const float* base = p + (size_t)zr * HH * WP;
        {
            int idx = tid;
            int yy = idx/(TX+2), xx = idx%(TX+2);
            int gy = refl(gy0-1+yy, HH);
            int gx = refl(gx0-1+xx, WW);
            const float* r = base + (size_t)gy*WP + gx;
            sm[buf][yy][xx] = r[1] - r[0];
        }
        {
            int idx = tid + TX*TY;
            if (idx < (TY+2)*(TX+2)){
                int yy = idx/(TX+2), xx = idx%(TX+2);
                int gy = refl(gy0-1+yy, HH);
                int gx = refl(gx0-1+xx, WW);
                const float* r = base + (size_t)gy*WP + gx;
                sm[buf][yy][xx] = r[1] - r[0];
            }
        }
    };
    auto read9 = [&](int buf, float q[9], float& ctr){
#pragma unroll
        for(int j=0;j<9;j++) q[j] = sm[buf][ty + j/3][tx + j%3];
        ctr = q[4];
    };

    float P0[9], P1[9], M0[10], M1[10];
    float c0, c1, dum;

    // prologue: plane z0-1 -> P1 (sorted), plane z0 -> P0 (sorted) + center
    load_plane(z0-1, 0); __syncthreads(); read9(0, P1, dum); sort9(P1);
    load_plane(z0,   1); __syncthreads(); read9(1, P0, c0);  sort9(P0);
    merge99_mid(P1, P0, M0);

    float lsum = 0.0f, lmax = 0.0f;
#pragma unroll 1
    for(int zi = 0; zi < ZC; zi += 2){
        const int z = z0 + zi;
        // even iteration: window {z-1,z,z+1}; AB=M0=merge(z-1,z); C=plane z+1
        load_plane(z+1, 0); __syncthreads(); read9(0, P1, c1); sort9(P1);
        {
            float med  = select13(M0, P1);
            float diff = c0 - med;
            lsum += diff*diff;
            lmax  = fmaxf(lmax, 1.0f - c0);
        }
        merge99_mid(P0, P1, M1);

        // odd iteration: window {z,z+1,z+2}
        load_plane(z+2, 1); __syncthreads(); read9(1, P0, c0); sort9(P0);
        {
            float med  = select13(M1, P0);
            float diff = c1 - med;
            lsum += diff*diff;
            lmax  = fmaxf(lmax, 1.0f - c1);
        }
        merge99_mid(P1, P0, M0);
    }

    // block reduction
#pragma unroll
    for(int off = 16; off; off >>= 1){
        lsum += __shfl_xor_sync(0xffffffffu, lsum, off);
        lmax  = fmaxf(lmax, __shfl_xor_sync(0xffffffffu, lmax, off));
    }
    __shared__ float rs[TY], rm[TY];
    if ((tid & 31) == 0){ rs[tid>>5] = lsum; rm[tid>>5] = lmax; }
    __syncthreads();
    if (tid == 0){
        float s = rs[0]+rs[1]+rs[2]+rs[3];
        float m = fmaxf(fmaxf(rs[0]*0.0f + rm[0], rm[1]), fmaxf(rm[2], rm[3]));
        atomicAdd(&g_sum, (double)s);
        atomicMax(&g_mon, __float_as_uint(m));   // m >= 0 always (lmax init 0)
    }
}

// ---------------- first-slice median: stage keys + histogram ----------------
__global__ void k_hist(const float* __restrict__ p){
    int i = blockIdx.x*blockDim.x + threadIdx.x;   // exact: 192*128 = N0
    unsigned key = f2key(p[(size_t)i * WP]);
    g_z0[i] = key;
    atomicAdd(&g_hist[key >> 22], 1);
}

// ---------------- scan + gather + select + finalize + reset (single block) --------------
__global__ void k_post(float* __restrict__ out){
    __shared__ int s[1024];
    __shared__ int sb[2];
    const int t = threadIdx.x;

    int h = g_hist[t];
    s[t] = h;
    __syncthreads();
    for (int off = 1; off < 1024; off <<= 1){
        int v = (t >= off) ? s[t-off] : 0;
        __syncthreads();
        s[t] += v;
        __syncthreads();
    }
    int incl = s[t], excl = incl - h;
    if (excl <= RANK && RANK < incl){ sb[0] = t; sb[1] = RANK - excl; }
    __syncthreads();
    const int bkt = sb[0];

    for (int i = t; i < N0; i += 1024){
        unsigned key = g_z0[i];
        if ((int)(key >> 22) == bkt){
            int pos = atomicAdd(&g_ccount, 1);
            g_cand[pos] = key;
        }
    }
    __syncthreads();
    const int m = g_ccount;
    const int r = sb[1];
    for (int i = t; i < m; i += 1024){
        unsigned ki = g_cand[i];
        int less = 0, eq = 0;
        for (int j = 0; j < m; j++){
            unsigned kj = g_cand[j];
            less += (kj < ki);
            eq   += (kj == ki);
        }
        if (less <= r && r < less + eq){
            float v = key2f(ki);
            out[2] = v*v;                         // loss_average
        }
    }
    __syncthreads();
    if (t == 0){
        out[0] = (float)(g_sum * (1.0/(double)TOTD));  // loss_smooth
        out[1] = __uint_as_float(g_mon);               // loss_mon
        g_sum = 0.0; g_mon = 0u; g_ccount = 0;         // reset for next replay
    }
    g_hist[t] = 0;
}

// ---------------- launch ----------------
extern "C" void kernel_launch(void* const* d_in, const int* in_sizes, int n_in,
                              void* d_out, int out_size) {
    const float* p = (const float*)d_in[0];
    float* out = (float*)d_out;

    {
        dim3 grid(WW/TX, HH/TY, DD/ZC);   // 6 x 48 x 8 = 2304 blocks
        dim3 block(TX, TY);
        k_median<<<grid, block>>>(p);
    }
    k_hist<<<N0/128, 128>>>(p);
    k_post<<<1, 1024>>>(out);
}